// round 2
// baseline (speedup 1.0000x reference)
#include <cuda_runtime.h>
#include <cuda_bf16.h>

#define K     2048
#define NROW  512
#define CW    32          // window size
#define NCH   64          // K / CW
#define DW    64          // warmup depth
#define NEGF  (-1.0e4f)

#define SMEM_BYTES 66432
// smem map (bytes):
//   bet : float4[2080] @ 0       (33280)  beta_{t+1} per t, padded chunk-transposed
//   ab  : float2[2080] @ 33280   (16640)  branch metrics (a,b)
//   A   : float [2048] @ 49920   ( 8192)  a-priori (La) buffer
//   Le  : float [2079] @ 58112   ( 8316)  BCJR output buffer (padded idx)

__device__ float g_S1[NROW * K];
__device__ float g_D1[NROW * K];
__device__ float g_S2[NROW * K];
__device__ float g_D2[NROW * K];

__device__ __forceinline__ int bidx(int t) { return (t & 31) * 65 + (t >> 5); }

// ---------------------------------------------------------------------------
// Prep kernel: encode both RSC streams via GF(2) linearity, build
//   gS1 = y1+y2, gD1 = y1-y2 (natural), gS2 = y1i+y3, gD2 = y1i-y3 (interleaved)
// ---------------------------------------------------------------------------
__global__ __launch_bounds__(256) void prep_kernel(
    const int* __restrict__ x, const float* __restrict__ n1,
    const float* __restrict__ n2, const float* __restrict__ n3,
    const int* __restrict__ perm)
{
    __shared__ unsigned xb[64], xib[64], pw[2][64], cst[2][64], ent[2][64];
    __shared__ float Y1[K];
    const int row = blockIdx.x, tid = threadIdx.x;
    const int base = row * K;

    // pack natural bits
    #pragma unroll
    for (int k = 0; k < 8; k++) {
        int t = tid + k * 256;
        unsigned bal = __ballot_sync(0xffffffffu, x[base + t] & 1);
        if ((tid & 31) == 0) xb[t >> 5] = bal;
    }
    __syncthreads();
    // pack interleaved bits: xi[i] = x[perm[i]]
    #pragma unroll
    for (int k = 0; k < 8; k++) {
        int i = tid + k * 256;
        int p = perm[i];
        int bit = (xb[p >> 5] >> (p & 31)) & 1;
        unsigned bal = __ballot_sync(0xffffffffu, bit);
        if ((tid & 31) == 0) xib[i >> 5] = bal;
    }
    __syncthreads();

    // chunk encode from zero state: parity p_t = u_t ^ s1(t); record final state
    if (tid < 128) {
        int seq = tid >> 6, j = tid & 63;
        unsigned bits = seq ? xib[j] : xb[j];
        unsigned s1 = 0, s2 = 0, p = 0;
        #pragma unroll
        for (int i = 0; i < 32; i++) {
            unsigned u = (bits >> i) & 1u;
            unsigned a = u ^ s1 ^ s2;
            p |= (a ^ s2) << i;
            s2 = s1; s1 = a;
        }
        pw[seq][j]  = p;
        cst[seq][j] = (s1 << 1) | s2;
    }
    __syncthreads();
    // entry-state scan: e_{j+1} = M^2 e_j ^ c_j   (M = [[1,1],[1,0]], M^3 = I)
    if (tid < 2) {
        unsigned e1 = 0, e2 = 0;
        for (int j = 0; j < 64; j++) {
            ent[tid][j] = (e1 << 1) | e2;
            unsigned c = cst[tid][j];
            unsigned ne1 = e2 ^ ((c >> 1) & 1u);
            unsigned ne2 = (e1 ^ e2) ^ (c & 1u);
            e1 = ne1; e2 = ne2;
        }
    }
    __syncthreads();
    // parity correction: s1(t) gains [M^t e]_1; masks by local t mod 3
    if (tid < 128) {
        int seq = tid >> 6, j = tid & 63;
        unsigned e = ent[seq][j];
        unsigned e1 = (e >> 1) & 1u, e2 = e & 1u;
        unsigned corr = (e1 ? 0x49249249u : 0u)
                      ^ ((e1 ^ e2) ? 0x92492492u : 0u)
                      ^ (e2 ? 0x24924924u : 0u);
        pw[seq][j] ^= corr;
    }
    __syncthreads();

    // channel outputs
    #pragma unroll
    for (int k = 0; k < 8; k++) {
        int t = tid + k * 256;
        float xv = (float)(2 * (int)((xb[t >> 5] >> (t & 31)) & 1u) - 1);
        float pv = (float)(2 * (int)((pw[0][t >> 5] >> (t & 31)) & 1u) - 1);
        float y1 = xv + n1[base + t];
        float y2 = pv + n2[base + t];
        Y1[t] = y1;
        g_S1[base + t] = y1 + y2;
        g_D1[base + t] = y1 - y2;
    }
    __syncthreads();
    #pragma unroll
    for (int k = 0; k < 8; k++) {
        int i = tid + k * 256;
        float y1i = Y1[perm[i]];
        float pv = (float)(2 * (int)((pw[1][i >> 5] >> (i & 31)) & 1u) - 1);
        float y3 = pv + n3[base + i];
        g_S2[base + i] = y1i + y3;
        g_D2[base + i] = y1i - y3;
    }
}

// ---------------------------------------------------------------------------
// One sliding-window max-log BCJR pass.
// Output Le[t] = LLR - (a+b) = LLR - (2*y_sys + La); if FIN, full LLR.
// ---------------------------------------------------------------------------
template <bool FIN>
__device__ __forceinline__ void bcjr(
    const float* __restrict__ gS, const float* __restrict__ gD,
    const float* __restrict__ A, float2* __restrict__ ab,
    float4* __restrict__ bet, float* __restrict__ Le, int tid)
{
    // P0: branch metrics
    #pragma unroll
    for (int k = 0; k < 8; k++) {
        int t = tid + k * 256;
        float la = 0.5f * A[t];
        ab[bidx(t)] = make_float2(gS[t] + la, gD[t] + la);
    }
    __syncthreads();

    float a0, a1, a2, a3;
    if (tid < NCH) {
        // forward warmup for window tid (windows 0..2 get the exact alpha0)
        int t0 = tid * CW - DW;
        float ini = (tid < 3) ? NEGF : 0.0f;
        a0 = 0.0f; a1 = ini; a2 = ini; a3 = ini;
        #pragma unroll 8
        for (int i = 0; i < DW; i++) {
            int t = t0 + i;
            if (t >= 0) {
                float2 g = ab[bidx(t)];
                float n0 = fmaxf(a0 - g.x, a1 + g.x);
                float n2 = fmaxf(a0 + g.x, a1 - g.x);
                float n1 = fmaxf(a2 + g.y, a3 - g.y);
                float n3 = fmaxf(a2 - g.y, a3 + g.y);
                a0 = n0; a1 = n1; a2 = n2; a3 = n3;
                if ((i & 7) == 7) { a1 -= a0; a2 -= a0; a3 -= a0; a0 = 0.0f; }
            }
        }
    } else if (tid < 2 * NCH) {
        // backward warmup + emit for window j (windows 61..63 exact from end)
        int j = tid - NCH;
        int tend = (j + 1) * CW;
        float b0 = 0.0f, b1 = 0.0f, b2 = 0.0f, b3 = 0.0f;
        #pragma unroll 8
        for (int i = 0; i < DW; i++) {
            int t = tend + DW - 1 - i;
            if (t < K) {
                float2 g = ab[bidx(t)];
                float n0 = fmaxf(b0 - g.x, b2 + g.x);
                float n1 = fmaxf(b2 - g.x, b0 + g.x);
                float n2 = fmaxf(b3 - g.y, b1 + g.y);
                float n3 = fmaxf(b1 - g.y, b3 + g.y);
                b0 = n0; b1 = n1; b2 = n2; b3 = n3;
                if ((i & 7) == 7) { b1 -= b0; b2 -= b0; b3 -= b0; b0 = 0.0f; }
            }
        }
        #pragma unroll 8
        for (int i = 0; i < CW; i++) {
            int t = tend - 1 - i;
            int ix = bidx(t);
            bet[ix] = make_float4(b0, b1, b2, b3);   // beta_{t+1}
            float2 g = ab[ix];
            float n0 = fmaxf(b0 - g.x, b2 + g.x);
            float n1 = fmaxf(b2 - g.x, b0 + g.x);
            float n2 = fmaxf(b3 - g.y, b1 + g.y);
            float n3 = fmaxf(b1 - g.y, b3 + g.y);
            b0 = n0; b1 = n1; b2 = n2; b3 = n3;
            if ((i & 7) == 7) { b1 -= b0; b2 -= b0; b3 -= b0; b0 = 0.0f; }
        }
    }
    __syncthreads();

    // P2: forward emit + LLR
    if (tid < NCH) {
        int t0 = tid * CW;
        #pragma unroll 4
        for (int i = 0; i < CW; i++) {
            int t = t0 + i;
            int ix = bidx(t);
            float2 g = ab[ix];
            float4 Bv = bet[ix];
            // u=1 branches: s0->2(+a), s1->0(+a), s2->1(+b), s3->3(+b)
            float m1 = fmaxf(fmaxf(a0 + Bv.z, a1 + Bv.x) + g.x,
                             fmaxf(a2 + Bv.y, a3 + Bv.w) + g.y);
            // u=0 branches: s0->0(-a), s1->2(-a), s2->3(-b), s3->1(-b)
            float m0 = fmaxf(fmaxf(a0 + Bv.x, a1 + Bv.z) - g.x,
                             fmaxf(a2 + Bv.w, a3 + Bv.y) - g.y);
            float llr = m1 - m0;
            Le[bidx(t)] = FIN ? llr : (llr - g.x - g.y);
            // advance alpha
            float n0 = fmaxf(a0 - g.x, a1 + g.x);
            float n2 = fmaxf(a0 + g.x, a1 - g.x);
            float n1 = fmaxf(a2 + g.y, a3 - g.y);
            float n3 = fmaxf(a2 - g.y, a3 + g.y);
            a0 = n0; a1 = n1; a2 = n2; a3 = n3;
            if ((i & 7) == 7) { a1 -= a0; a2 -= a0; a3 -= a0; a0 = 0.0f; }
        }
    }
}

// ---------------------------------------------------------------------------
// Main kernel: 6 turbo iterations, one CTA per row
// ---------------------------------------------------------------------------
__global__ __launch_bounds__(256, 3) void turbo_kernel(
    const int* __restrict__ perm, float* __restrict__ out)
{
    extern __shared__ char smraw[];
    float4* bet = (float4*)(smraw);
    float2* ab  = (float2*)(smraw + 33280);
    float*  A   = (float* )(smraw + 49920);
    float*  Le  = (float* )(smraw + 58112);
    const int row = blockIdx.x, tid = threadIdx.x;
    const float* gS1 = g_S1 + row * K;
    const float* gD1 = g_D1 + row * K;
    const float* gS2 = g_S2 + row * K;
    const float* gD2 = g_D2 + row * K;

    #pragma unroll
    for (int k = 0; k < 8; k++) A[tid + k * 256] = 0.0f;
    __syncthreads();

    #pragma unroll 1
    for (int it = 0; it < 5; it++) {
        bcjr<false>(gS1, gD1, A, ab, bet, Le, tid);
        __syncthreads();
        #pragma unroll
        for (int k = 0; k < 8; k++) { int i = tid + k * 256; A[i] = Le[bidx(perm[i])]; }
        __syncthreads();
        bcjr<false>(gS2, gD2, A, ab, bet, Le, tid);
        __syncthreads();
        #pragma unroll
        for (int k = 0; k < 8; k++) { int i = tid + k * 256; A[perm[i]] = Le[bidx(i)]; }
        __syncthreads();
    }
    // final iteration: decoder 2 emits full LLR
    bcjr<false>(gS1, gD1, A, ab, bet, Le, tid);
    __syncthreads();
    #pragma unroll
    for (int k = 0; k < 8; k++) { int i = tid + k * 256; A[i] = Le[bidx(perm[i])]; }
    __syncthreads();
    bcjr<true>(gS2, gD2, A, ab, bet, Le, tid);
    __syncthreads();

    float* orow = out + row * K;
    #pragma unroll
    for (int k = 0; k < 8; k++) { int i = tid + k * 256; orow[perm[i]] = Le[bidx(i)]; }
}

// ---------------------------------------------------------------------------
extern "C" void kernel_launch(void* const* d_in, const int* in_sizes, int n_in,
                              void* d_out, int out_size)
{
    const int*   x    = (const int*)  d_in[0];
    const float* n1   = (const float*)d_in[1];
    const float* n2   = (const float*)d_in[2];
    const float* n3   = (const float*)d_in[3];
    const int*   perm = (const int*)  d_in[4];
    float* out = (float*)d_out;

    prep_kernel<<<NROW, 256>>>(x, n1, n2, n3, perm);

    cudaFuncSetAttribute(turbo_kernel,
                         cudaFuncAttributeMaxDynamicSharedMemorySize, SMEM_BYTES);
    turbo_kernel<<<NROW, 256, SMEM_BYTES>>>(perm, out);
}

// round 4
// speedup vs baseline: 1.8587x; 1.8587x over previous
#include <cuda_runtime.h>
#include <cuda_bf16.h>

#define K     2048
#define NROW  512
#define NT    128          // threads per CTA
#define CW    32           // window size
#define NCH   64           // K / CW
#define DW    64           // warmup depth
#define PADB  64           // ab pad on each side (== DW)
#define NEGF  (-1.0e4f)

#define SMEM_BYTES 50944
// smem map (bytes):
//   bet : float4[2080] @ 0       (33280)  beta_{t+1}; emit aliases Le into .x
//   abp : float2[2208] @ 33280   (17664)  branch metrics, padded [-64, K+64)
//        abp[.x] doubles as the La staging slot between BCJRs

__device__ float2 g_P1[NROW * K];   // (y1+y2, y1-y2)  natural order
__device__ float2 g_P2[NROW * K];   // (y1i+y3, y1i-y3) interleaved order

__device__ __forceinline__ int bidx(int t)  { return (t & 31) * 65 + (t >> 5); }
__device__ __forceinline__ int pidx(int ts) { return (ts & 31) * 69 + (ts >> 5); }

// ---------------------------------------------------------------------------
// One sliding-window max-log BCJR pass.
// On entry: abp[pidx(t+PADB)].x holds La[t].  On exit: bet[bidx(t)].x holds
// extrinsic Le[t] = LLR - (2*y_sys + La)   (full LLR if FIN).
// ---------------------------------------------------------------------------
template<bool FIN>
__device__ __forceinline__ void bcjr(const float2* __restrict__ g,
                                     float2* __restrict__ abp,
                                     float4* __restrict__ bet, int tid)
{
    // P0: branch metrics  a = S + La/2, b = D + La/2  (in-place over staged La)
    #pragma unroll
    for (int k = 0; k < K / NT; k++) {
        int t  = tid + k * NT;
        int ix = pidx(t + PADB);
        float la = 0.5f * abp[ix].x;
        float2 sd = g[t];
        abp[ix] = make_float2(sd.x + la, sd.y + la);
    }
    __syncthreads();

    float a0, a1, a2, a3;
    if (tid < NCH) {
        // forward warmup, branch-free (pads at ts<64 preserve exact/uniform init)
        float ini = (tid < 3) ? NEGF : 0.0f;
        a0 = 0.0f; a1 = ini; a2 = ini; a3 = ini;
        int ts0 = tid * CW;                    // == (window start - DW) + PADB
        #pragma unroll 8
        for (int i = 0; i < DW; i++) {
            float2 gg = abp[pidx(ts0 + i)];
            float n0 = fmaxf(a0 - gg.x, a1 + gg.x);
            float n2 = fmaxf(a0 + gg.x, a1 - gg.x);
            float n1 = fmaxf(a2 + gg.y, a3 - gg.y);
            float n3 = fmaxf(a2 - gg.y, a3 + gg.y);
            a0 = n0; a1 = n1; a2 = n2; a3 = n3;
            if ((i & 7) == 7) { a1 -= a0; a2 -= a0; a3 -= a0; a0 = 0.0f; }
        }
    } else {
        // backward warmup (pads at ts>=K+64, g=0 preserves uniform) + store
        int j = tid - NCH;
        int tend = (j + 1) * CW;
        float b0 = 0.0f, b1 = 0.0f, b2 = 0.0f, b3 = 0.0f;
        int tsv = tend + PADB + DW - 1;
        #pragma unroll 8
        for (int i = 0; i < DW; i++) {
            float2 gg = abp[pidx(tsv - i)];
            float n0 = fmaxf(b0 - gg.x, b2 + gg.x);
            float n1 = fmaxf(b2 - gg.x, b0 + gg.x);
            float n2 = fmaxf(b3 - gg.y, b1 + gg.y);
            float n3 = fmaxf(b1 - gg.y, b3 + gg.y);
            b0 = n0; b1 = n1; b2 = n2; b3 = n3;
            if ((i & 7) == 7) { b1 -= b0; b2 -= b0; b3 -= b0; b0 = 0.0f; }
        }
        #pragma unroll 8
        for (int i = 0; i < CW; i++) {
            int t = tend - 1 - i;
            int ixb = bidx(t);
            bet[ixb] = make_float4(b0, b1, b2, b3);   // beta_{t+1}
            float2 gg = abp[pidx(t + PADB)];
            float n0 = fmaxf(b0 - gg.x, b2 + gg.x);
            float n1 = fmaxf(b2 - gg.x, b0 + gg.x);
            float n2 = fmaxf(b3 - gg.y, b1 + gg.y);
            float n3 = fmaxf(b1 - gg.y, b3 + gg.y);
            b0 = n0; b1 = n1; b2 = n2; b3 = n3;
            if ((i & 7) == 7) { b1 -= b0; b2 -= b0; b3 -= b0; b0 = 0.0f; }
        }
    }
    __syncthreads();

    // P2: forward emit; Le written into bet.x after the beta read
    if (tid < NCH) {
        int t0 = tid * CW;
        #pragma unroll 4
        for (int i = 0; i < CW; i++) {
            int t = t0 + i;
            int ixb = bidx(t);
            float2 gg = abp[pidx(t + PADB)];
            float4 Bv = bet[ixb];
            float m1 = fmaxf(fmaxf(a0 + Bv.z, a1 + Bv.x) + gg.x,
                             fmaxf(a2 + Bv.y, a3 + Bv.w) + gg.y);
            float m0 = fmaxf(fmaxf(a0 + Bv.x, a1 + Bv.z) - gg.x,
                             fmaxf(a2 + Bv.w, a3 + Bv.y) - gg.y);
            float llr = m1 - m0;
            bet[ixb].x = FIN ? llr : (llr - gg.x - gg.y);
            float n0 = fmaxf(a0 - gg.x, a1 + gg.x);
            float n2 = fmaxf(a0 + gg.x, a1 - gg.x);
            float n1 = fmaxf(a2 + gg.y, a3 - gg.y);
            float n3 = fmaxf(a2 - gg.y, a3 + gg.y);
            a0 = n0; a1 = n1; a2 = n2; a3 = n3;
            if ((i & 7) == 7) { a1 -= a0; a2 -= a0; a3 -= a0; a0 = 0.0f; }
        }
    }
}

// ---------------------------------------------------------------------------
// Fused kernel: encode + channel prep + 6 turbo iterations. One CTA per row.
// ---------------------------------------------------------------------------
__global__ __launch_bounds__(NT, 4) void turbo_kernel(
    const int* __restrict__ x, const float* __restrict__ n1,
    const float* __restrict__ n2, const float* __restrict__ n3,
    const int* __restrict__ perm, float* __restrict__ out)
{
    extern __shared__ char smraw[];
    float4* bet = (float4*)(smraw);
    float2* abp = (float2*)(smraw + 33280);
    // prep scratch (inside bet region, dead before first BCJR writes bet)
    float*    Y1  = (float*)smraw;                    // [2048]
    unsigned* xb  = (unsigned*)(smraw + 8192);        // [64]
    unsigned* xib = (unsigned*)(smraw + 8448);        // [64]
    unsigned (*pw)[64]  = (unsigned(*)[64])(smraw + 8704);
    unsigned (*cst)[64] = (unsigned(*)[64])(smraw + 9216);
    unsigned (*ent)[64] = (unsigned(*)[64])(smraw + 9728);

    const int row = blockIdx.x, tid = threadIdx.x;
    const int base = row * K;

    int permr[K / NT];
    #pragma unroll
    for (int k = 0; k < K / NT; k++) permr[k] = perm[tid + k * NT];

    // ---- ab pads (written once; never overwritten by P0/staging) ----
    if (tid < PADB) {
        abp[pidx(tid)] = make_float2(NEGF, NEGF);             // fwd pads t<0
        abp[pidx(K + PADB + tid)] = make_float2(0.0f, 0.0f);  // bwd pads t>=K
    }
    // ---- stage La = 0 for first BCJR ----
    #pragma unroll
    for (int k = 0; k < K / NT; k++)
        abp[pidx(tid + k * NT + PADB)] = make_float2(0.0f, 0.0f);

    // ---- encode: pack bits ----
    #pragma unroll
    for (int k = 0; k < K / NT; k++) {
        int t = tid + k * NT;
        unsigned bal = __ballot_sync(0xffffffffu, x[base + t] & 1);
        if ((tid & 31) == 0) xb[t >> 5] = bal;
    }
    __syncthreads();
    #pragma unroll
    for (int k = 0; k < K / NT; k++) {
        int i = tid + k * NT;
        int p = permr[k];
        int bit = (xb[p >> 5] >> (p & 31)) & 1;
        unsigned bal = __ballot_sync(0xffffffffu, bit);
        if ((tid & 31) == 0) xib[i >> 5] = bal;
    }
    __syncthreads();

    // chunk encode from zero state (all 128 threads: 2 sequences x 64 chunks)
    {
        int seq = tid >> 6, j = tid & 63;
        unsigned bits = seq ? xib[j] : xb[j];
        unsigned s1 = 0, s2 = 0, p = 0;
        #pragma unroll
        for (int i = 0; i < 32; i++) {
            unsigned u = (bits >> i) & 1u;
            unsigned a = u ^ s1 ^ s2;
            p |= (a ^ s2) << i;
            s2 = s1; s1 = a;
        }
        pw[seq][j]  = p;
        cst[seq][j] = (s1 << 1) | s2;
    }
    __syncthreads();
    if (tid < 2) {  // entry-state scan (M^3 = I)
        unsigned e1 = 0, e2 = 0;
        for (int j = 0; j < 64; j++) {
            ent[tid][j] = (e1 << 1) | e2;
            unsigned c = cst[tid][j];
            unsigned ne1 = e2 ^ ((c >> 1) & 1u);
            unsigned ne2 = (e1 ^ e2) ^ (c & 1u);
            e1 = ne1; e2 = ne2;
        }
    }
    __syncthreads();
    {   // parity correction by entry state
        int seq = tid >> 6, j = tid & 63;
        unsigned e = ent[seq][j];
        unsigned e1 = (e >> 1) & 1u, e2 = e & 1u;
        unsigned corr = (e1 ? 0x49249249u : 0u)
                      ^ ((e1 ^ e2) ? 0x92492492u : 0u)
                      ^ (e2 ? 0x24924924u : 0u);
        pw[seq][j] ^= corr;
    }
    __syncthreads();

    // ---- channel combinations ----
    #pragma unroll
    for (int k = 0; k < K / NT; k++) {
        int t = tid + k * NT;
        float xv = (float)(2 * (int)((xb[t >> 5] >> (t & 31)) & 1u) - 1);
        float pv = (float)(2 * (int)((pw[0][t >> 5] >> (t & 31)) & 1u) - 1);
        float y1 = xv + n1[base + t];
        float y2 = pv + n2[base + t];
        Y1[t] = y1;
        g_P1[base + t] = make_float2(y1 + y2, y1 - y2);
    }
    __syncthreads();
    #pragma unroll
    for (int k = 0; k < K / NT; k++) {
        int i = tid + k * NT;
        float y1i = Y1[permr[k]];
        float pv = (float)(2 * (int)((pw[1][i >> 5] >> (i & 31)) & 1u) - 1);
        float y3 = pv + n3[base + i];
        g_P2[base + i] = make_float2(y1i + y3, y1i - y3);
    }
    __syncthreads();

    const float2* gP1 = g_P1 + base;
    const float2* gP2 = g_P2 + base;

    // ---- 6 turbo iterations ----
    #pragma unroll 1
    for (int it = 0; it < 5; it++) {
        bcjr<false>(gP1, abp, bet, tid);
        __syncthreads();
        #pragma unroll
        for (int k = 0; k < K / NT; k++) {              // A2[i] = Le1[perm[i]]
            int i = tid + k * NT;
            abp[pidx(i + PADB)].x = bet[bidx(permr[k])].x;
        }
        __syncthreads();
        bcjr<false>(gP2, abp, bet, tid);
        __syncthreads();
        #pragma unroll
        for (int k = 0; k < K / NT; k++) {              // A1[perm[i]] = Le2[i]
            int i = tid + k * NT;
            abp[pidx(permr[k] + PADB)].x = bet[bidx(i)].x;
        }
        __syncthreads();
    }
    bcjr<false>(gP1, abp, bet, tid);
    __syncthreads();
    #pragma unroll
    for (int k = 0; k < K / NT; k++) {
        int i = tid + k * NT;
        abp[pidx(i + PADB)].x = bet[bidx(permr[k])].x;
    }
    __syncthreads();
    bcjr<true>(gP2, abp, bet, tid);
    __syncthreads();

    float* orow = out + base;
    #pragma unroll
    for (int k = 0; k < K / NT; k++) {                  // out[perm[i]] = L2[i]
        int i = tid + k * NT;
        orow[permr[k]] = bet[bidx(i)].x;
    }
}

// ---------------------------------------------------------------------------
extern "C" void kernel_launch(void* const* d_in, const int* in_sizes, int n_in,
                              void* d_out, int out_size)
{
    const int*   x    = (const int*)  d_in[0];
    const float* n1   = (const float*)d_in[1];
    const float* n2   = (const float*)d_in[2];
    const float* n3   = (const float*)d_in[3];
    const int*   perm = (const int*)  d_in[4];
    float* out = (float*)d_out;

    cudaFuncSetAttribute(turbo_kernel,
                         cudaFuncAttributeMaxDynamicSharedMemorySize, SMEM_BYTES);
    turbo_kernel<<<NROW, NT, SMEM_BYTES>>>(x, n1, n2, n3, perm, out);
}